// round 5
// baseline (speedup 1.0000x reference)
#include <cuda_runtime.h>
#include <cuda_bf16.h>
#include <math.h>
#include <stdint.h>

// ---------------- problem constants ----------------
#define LTOK 8192
#define HDIM 1280
#define NHEAD 16
#define HEADD 80
#define MHID 3420
#define MH_P 3424          // padded leading dim (16B-aligned bf16 rows)
#define NBLK 4
#define NWIN 128
#define PDIM 1176
#define DMODEL 3584
#define H4 5120
#define LMERG 2048

// ---------------- fp32 scratch ----------------
static constexpr long SZ_LH  = (long)LTOK * HDIM;
static constexpr long SZ_L3H = (long)LTOK * 3 * HDIM;
static constexpr long SZ_LMH = (long)LTOK * MHID;

static constexpr long F_X    = 0;
static constexpr long F_RES  = F_X   + SZ_LH;
static constexpr long F_HB   = F_RES + SZ_LH;
static constexpr long F_QKV  = F_HB  + SZ_LH;
static constexpr long F_GATE = F_QKV + SZ_L3H;
static constexpr long F_UP   = F_GATE + SZ_LMH;
static constexpr long F_TOTAL = F_UP + SZ_LMH;
__device__ float g_f32[F_TOTAL];

// ---------------- bf16 scratch (hi/lo pairs) ----------------
static constexpr long SZ_XS  = (long)LTOK * PDIM;
static constexpr long SZ_PW  = (long)PDIM * HDIM;
static constexpr long SZ_QW  = (long)NBLK * HDIM * 3*HDIM;
static constexpr long SZ_PRW = (long)NBLK * HDIM * HDIM;
static constexpr long SZ_GWP = (long)NBLK * HDIM * MH_P;   // padded
static constexpr long SZ_DW  = (long)NBLK * MHID * HDIM;
static constexpr long SZ_M0W = (long)H4 * H4;
static constexpr long SZ_M2W = (long)H4 * DMODEL;
static constexpr long SZ_SHP = (long)LTOK * MH_P;          // padded swiglu out

static constexpr long B_XH  = 0;
static constexpr long B_XL  = B_XH + SZ_XS;
static constexpr long B_NH  = B_XL + SZ_XS;
static constexpr long B_NL  = B_NH + SZ_LH;
static constexpr long B_AH  = B_NL + SZ_LH;
static constexpr long B_AL  = B_AH + SZ_LH;
static constexpr long B_SH  = B_AL + SZ_LH;
static constexpr long B_SL  = B_SH + SZ_SHP;
static constexpr long B_PW  = B_SL + SZ_SHP;
static constexpr long B_QW  = B_PW + 2*SZ_PW;
static constexpr long B_PRW = B_QW + 2*SZ_QW;
static constexpr long B_GW  = B_PRW + 2*SZ_PRW;
static constexpr long B_UW  = B_GW + 2*SZ_GWP;
static constexpr long B_DW  = B_UW + 2*SZ_GWP;
static constexpr long B_M0W = B_DW + 2*SZ_DW;
static constexpr long B_M2W = B_M0W + 2*SZ_M0W;
static constexpr long B_TOTAL = B_M2W + 2*SZ_M2W;
__device__ __nv_bfloat16 g_bf16[B_TOTAL];

// ---------------- PTX helpers (base sm_103 target only!) ----------------
__device__ __forceinline__ uint32_t smem_to_u32(const void* p) {
    uint32_t a;
    asm("{ .reg .u64 t; cvta.to.shared.u64 t, %1; cvt.u32.u64 %0, t; }" : "=r"(a) : "l"(p));
    return a;
}
__device__ __forceinline__ void cp16(uint32_t dst, const void* src, int bytes) {
    asm volatile("cp.async.cg.shared.global [%0], [%1], 16, %2;"
                 :: "r"(dst), "l"(src), "r"(bytes));
}
#define CP_COMMIT() asm volatile("cp.async.commit_group;" ::: "memory")
#define CP_WAIT2()  asm volatile("cp.async.wait_group 2;" ::: "memory")

__device__ __forceinline__ void ldsm_x4(uint32_t r[4], uint32_t addr) {
    asm volatile("ldmatrix.sync.aligned.m8n8.x4.shared.b16 {%0,%1,%2,%3}, [%4];"
                 : "=r"(r[0]), "=r"(r[1]), "=r"(r[2]), "=r"(r[3]) : "r"(addr));
}
__device__ __forceinline__ void ldsm_x4t(uint32_t r[4], uint32_t addr) {
    asm volatile("ldmatrix.sync.aligned.m8n8.x4.trans.shared.b16 {%0,%1,%2,%3}, [%4];"
                 : "=r"(r[0]), "=r"(r[1]), "=r"(r[2]), "=r"(r[3]) : "r"(addr));
}
__device__ __forceinline__ void mma_bf16(float c[4], const uint32_t a[4],
                                         uint32_t b0, uint32_t b1) {
    asm volatile(
        "mma.sync.aligned.m16n8k16.row.col.f32.bf16.bf16.f32 "
        "{%0,%1,%2,%3}, {%4,%5,%6,%7}, {%8,%9}, {%0,%1,%2,%3};"
        : "+f"(c[0]), "+f"(c[1]), "+f"(c[2]), "+f"(c[3])
        : "r"(a[0]), "r"(a[1]), "r"(a[2]), "r"(a[3]), "r"(b0), "r"(b1));
}

// ---------------- tensor-core GEMM (bf16x3 split, fp32 accum) ----------------
enum { E_NONE = 0, E_BIAS = 1, E_BIAS_RES = 2, E_GELU_SPLIT = 3 };

// Tiles: BM=128, BN=128, BK=32. 16 warps in 4(M)x4(N); warp tile 32x32.
#define A_STRIDE 40
#define B_STRIDE 136
#define A_TILE_B (128 * A_STRIDE * 2)      // 10240
#define B_TILE_B (32 * B_STRIDE * 2)       // 8704
#define STAGE_B  (2 * A_TILE_B + 2 * B_TILE_B)  // 37888
#define OFF_AH 0
#define OFF_AL A_TILE_B
#define OFF_BH (2 * A_TILE_B)
#define OFF_BL (2 * A_TILE_B + B_TILE_B)
#define GEMM_SMEM (3 * STAGE_B)            // 113664
#define GT 512                             // GEMM threads

template<int EPI>
__global__ void __launch_bounds__(GT) tcgemm_kernel(
    const __nv_bfloat16* __restrict__ Ah, const __nv_bfloat16* __restrict__ Al,
    const __nv_bfloat16* __restrict__ Bh, const __nv_bfloat16* __restrict__ Bl,
    const float* __restrict__ bias, const float* __restrict__ res,
    float* __restrict__ C, __nv_bfloat16* __restrict__ Oh, __nv_bfloat16* __restrict__ Ol,
    int M, int N, int K, int lda, int ldb, int ldc)
{
    extern __shared__ __align__(16) char sm[];
    const uint32_t smem_u = smem_to_u32(sm);
    const int tid = threadIdx.x;
    const int lane = tid & 31, wid = tid >> 5;
    const int wm = wid >> 2, wn = wid & 3;        // 4 x 4 warp grid
    const int row0 = blockIdx.y * 128, col0 = blockIdx.x * 128;

    const int nc = (K + 31) / 32;

    // -------- stage loader (512 threads: 1 vec per half per matrix) --------
    auto load_stage = [&](int st, int c) {
        const uint32_t sbase = smem_u + st * STAGE_B;
        const int k0 = c * 32;
        // A tiles: 128 rows x 32 bf16 (4 x 16B per row); 512 vecs per half
        #pragma unroll
        for (int h = 0; h < 2; ++h) {
            const __nv_bfloat16* src = h ? Al : Ah;
            const uint32_t dbase = sbase + (h ? OFF_AL : OFF_AH);
            int r = tid >> 2, q = tid & 3;
            int gr = row0 + r;
            int gk = k0 + q * 8;
            int bytes = (K - gk) * 2;
            bytes = bytes < 0 ? 0 : (bytes > 16 ? 16 : bytes);
            const __nv_bfloat16* g = src + (long)gr * lda + (bytes > 0 ? gk : 0);
            cp16(dbase + r * (A_STRIDE * 2) + q * 16, g, bytes);
        }
        // B tiles: 32 rows x 128 bf16 (16 x 16B per row); 512 vecs per half
        #pragma unroll
        for (int h = 0; h < 2; ++h) {
            const __nv_bfloat16* src = h ? Bl : Bh;
            const uint32_t dbase = sbase + (h ? OFF_BL : OFF_BH);
            int r = tid >> 4, q = tid & 15;
            int gk = k0 + r;
            int gc = col0 + q * 8;
            int bytes = (N - gc) * 2;
            bytes = bytes < 0 ? 0 : (bytes > 16 ? 16 : bytes);
            if (gk >= K) bytes = 0;
            const __nv_bfloat16* g = src + (long)(gk < K ? gk : 0) * ldb + (bytes > 0 ? gc : 0);
            cp16(dbase + r * (B_STRIDE * 2) + q * 16, g, bytes);
        }
    };

    // -------- ldmatrix lane offsets --------
    const int a_row = lane & 15;
    const int a_kh = (lane >> 4) * 8;
    const int b_g = lane >> 3, b_l = lane & 7;
    const int b_k = (b_g & 1) * 8 + b_l;
    const int b_n = (b_g >> 1) * 8;

    float acc[2][4][4];
    #pragma unroll
    for (int i = 0; i < 2; ++i)
        #pragma unroll
        for (int j = 0; j < 4; ++j)
            #pragma unroll
            for (int r = 0; r < 4; ++r) acc[i][j][r] = 0.f;

    // prologue
    #pragma unroll
    for (int s = 0; s < 3; ++s) {
        if (s < nc) load_stage(s, s);
        CP_COMMIT();
    }

    for (int c = 0; c < nc; ++c) {
        CP_WAIT2();
        __syncthreads();
        const int st = c % 3;
        const uint32_t sbase = smem_u + st * STAGE_B;
        const uint32_t aB[2] = { sbase + OFF_AH, sbase + OFF_AL };
        const uint32_t bB[2] = { sbase + OFF_BH, sbase + OFF_BL };

        #pragma unroll
        for (int ks = 0; ks < 2; ++ks) {
            uint32_t af[2][2][4];
            #pragma unroll
            for (int h = 0; h < 2; ++h)
                #pragma unroll
                for (int i = 0; i < 2; ++i)
                    ldsm_x4(af[h][i],
                        aB[h] + 2u * ((wm * 32 + i * 16 + a_row) * A_STRIDE + ks * 16 + a_kh));
            uint32_t bf[2][2][4];
            #pragma unroll
            for (int h = 0; h < 2; ++h)
                #pragma unroll
                for (int j2 = 0; j2 < 2; ++j2)
                    ldsm_x4t(bf[h][j2],
                        bB[h] + 2u * ((ks * 16 + b_k) * B_STRIDE + wn * 32 + j2 * 16 + b_n));

            // D += Ah*Bh + Ah*Bl + Al*Bh
            #pragma unroll
            for (int i = 0; i < 2; ++i)
                #pragma unroll
                for (int j = 0; j < 4; ++j)
                    mma_bf16(acc[i][j], af[0][i], bf[0][j >> 1][(j & 1) * 2], bf[0][j >> 1][(j & 1) * 2 + 1]);
            #pragma unroll
            for (int i = 0; i < 2; ++i)
                #pragma unroll
                for (int j = 0; j < 4; ++j)
                    mma_bf16(acc[i][j], af[0][i], bf[1][j >> 1][(j & 1) * 2], bf[1][j >> 1][(j & 1) * 2 + 1]);
            #pragma unroll
            for (int i = 0; i < 2; ++i)
                #pragma unroll
                for (int j = 0; j < 4; ++j)
                    mma_bf16(acc[i][j], af[1][i], bf[0][j >> 1][(j & 1) * 2], bf[0][j >> 1][(j & 1) * 2 + 1]);
        }
        __syncthreads();
        if (c + 3 < nc) load_stage(st, c + 3);
        CP_COMMIT();
    }

    // -------- epilogue --------
    const int g = lane >> 2, t = lane & 3;
    #pragma unroll
    for (int i = 0; i < 2; ++i) {
        #pragma unroll
        for (int j = 0; j < 4; ++j) {
            int col = col0 + wn * 32 + j * 8 + t * 2;
            if (col >= N) continue;
            float b0 = 0.f, b1 = 0.f;
            if (EPI != E_NONE) { b0 = bias[col]; b1 = bias[col + 1]; }
            #pragma unroll
            for (int rr = 0; rr < 2; ++rr) {
                int row = row0 + wm * 32 + i * 16 + g + rr * 8;
                if (row >= M) continue;
                float v0 = acc[i][j][rr * 2 + 0] + b0;
                float v1 = acc[i][j][rr * 2 + 1] + b1;
                long idx = (long)row * ldc + col;
                if (EPI == E_BIAS_RES) { v0 += res[idx]; v1 += res[idx + 1]; }
                if (EPI == E_GELU_SPLIT) {
                    v0 = 0.5f * v0 * (1.f + erff(v0 * 0.70710678118654752f));
                    v1 = 0.5f * v1 * (1.f + erff(v1 * 0.70710678118654752f));
                    __nv_bfloat16 h0 = __float2bfloat16(v0);
                    __nv_bfloat16 h1 = __float2bfloat16(v1);
                    Oh[idx] = h0; Oh[idx + 1] = h1;
                    Ol[idx]     = __float2bfloat16(v0 - __bfloat162float(h0));
                    Ol[idx + 1] = __float2bfloat16(v1 - __bfloat162float(h1));
                } else {
                    float2 o = make_float2(v0, v1);
                    *reinterpret_cast<float2*>(C + idx) = o;
                }
            }
        }
    }
}

// ---------------- fused windowed attention with inline RoPE (fp32) ----------------
#define SP 81
#define ATTN_SMEM ((3 * 64 * SP + 64 * 64) * 4)

__global__ void __launch_bounds__(256) attn_kernel(
    const float* __restrict__ qkv, const float* __restrict__ cosb,
    const float* __restrict__ sinb, __nv_bfloat16* __restrict__ outH,
    __nv_bfloat16* __restrict__ outL)
{
    extern __shared__ float smf[];
    float* q = smf;
    float* k = smf + 64 * SP;
    float* v = smf + 2 * 64 * SP;
    float* s = smf + 3 * 64 * SP;

    const int w = blockIdx.x >> 4;
    const int h = blockIdx.x & 15;
    const int tid = threadIdx.x;
    const float scale = 0.11180339887498949f;

    for (int e = tid; e < 64 * 80; e += 256) {
        int t = e / 80, j = e % 80;
        int l = w * 64 + t;
        long base = (long)l * (3 * HDIM) + h * 80;
        float c = cosb[l * 80 + j], sn = sinb[l * 80 + j];
        float qv = qkv[base + j];
        float qr = (j < 40) ? -qkv[base + j + 40] : qkv[base + j - 40];
        q[t * SP + j] = qv * c + qr * sn;
        float kv = qkv[base + HDIM + j];
        float kr = (j < 40) ? -qkv[base + HDIM + j + 40] : qkv[base + HDIM + j - 40];
        k[t * SP + j] = kv * c + kr * sn;
        v[t * SP + j] = qkv[base + 2 * HDIM + j];
    }
    __syncthreads();

    {
        const int tx = tid & 15, ty = tid >> 4;
        float acc[4][4] = {};
        for (int d = 0; d < 80; d++) {
            float qa[4], kb[4];
            #pragma unroll
            for (int i = 0; i < 4; i++) qa[i] = q[(ty * 4 + i) * SP + d];
            #pragma unroll
            for (int j = 0; j < 4; j++) kb[j] = k[(tx * 4 + j) * SP + d];
            #pragma unroll
            for (int i = 0; i < 4; i++)
                #pragma unroll
                for (int j = 0; j < 4; j++)
                    acc[i][j] += qa[i] * kb[j];
        }
        #pragma unroll
        for (int i = 0; i < 4; i++)
            #pragma unroll
            for (int j = 0; j < 4; j++)
                s[(ty * 4 + i) * 64 + tx * 4 + j] = acc[i][j] * scale;
    }
    __syncthreads();

    {
        const int warp = tid >> 5, lane = tid & 31;
        for (int r = warp; r < 64; r += 8) {
            float x0 = s[r * 64 + lane], x1 = s[r * 64 + 32 + lane];
            float mx = fmaxf(x0, x1);
            #pragma unroll
            for (int o = 16; o > 0; o >>= 1) mx = fmaxf(mx, __shfl_xor_sync(~0u, mx, o));
            float e0 = __expf(x0 - mx), e1 = __expf(x1 - mx);
            float sum = e0 + e1;
            #pragma unroll
            for (int o = 16; o > 0; o >>= 1) sum += __shfl_xor_sync(~0u, sum, o);
            float inv = 1.f / sum;
            s[r * 64 + lane] = e0 * inv;
            s[r * 64 + 32 + lane] = e1 * inv;
        }
    }
    __syncthreads();

    {
        const int tx = tid & 15, ty = tid >> 4;
        float acc[4][5] = {};
        for (int kk = 0; kk < 64; kk++) {
            float sa[4], vb[5];
            #pragma unroll
            for (int i = 0; i < 4; i++) sa[i] = s[(ty * 4 + i) * 64 + kk];
            #pragma unroll
            for (int j = 0; j < 5; j++) vb[j] = v[kk * SP + tx * 5 + j];
            #pragma unroll
            for (int i = 0; i < 4; i++)
                #pragma unroll
                for (int j = 0; j < 5; j++)
                    acc[i][j] += sa[i] * vb[j];
        }
        #pragma unroll
        for (int i = 0; i < 4; i++) {
            long obase = (long)(w * 64 + ty * 4 + i) * HDIM + h * 80 + tx * 5;
            #pragma unroll
            for (int j = 0; j < 5; j++) {
                float val = acc[i][j];
                __nv_bfloat16 hh = __float2bfloat16(val);
                outH[obase + j] = hh;
                outL[obase + j] = __float2bfloat16(val - __bfloat162float(hh));
            }
        }
    }
}

// ---------------- fused (optional add) + RMSNorm, bf16 hi/lo out ----------------
__global__ void __launch_bounds__(256) rmsnorm_kernel(
    const float* __restrict__ a, const float* __restrict__ b,
    const float* __restrict__ w, float* __restrict__ sum_out,
    __nv_bfloat16* __restrict__ nh, __nv_bfloat16* __restrict__ nl)
{
    __shared__ float sv[HDIM];
    __shared__ float red[8];
    __shared__ float s_scale;
    const int row = blockIdx.x, tid = threadIdx.x;
    const long base = (long)row * HDIM;
    float ss = 0.f;
    for (int j = tid; j < HDIM; j += 256) {
        float v = a[base + j];
        if (b) v += b[base + j];
        sv[j] = v;
        if (sum_out) sum_out[base + j] = v;
        ss += v * v;
    }
    #pragma unroll
    for (int o = 16; o > 0; o >>= 1) ss += __shfl_xor_sync(~0u, ss, o);
    if ((tid & 31) == 0) red[tid >> 5] = ss;
    __syncthreads();
    if (tid == 0) {
        float t = 0.f;
        #pragma unroll
        for (int i = 0; i < 8; i++) t += red[i];
        s_scale = rsqrtf(t / (float)HDIM + 1e-6f);
    }
    __syncthreads();
    float sc = s_scale;
    for (int j = tid; j < HDIM; j += 256) {
        float v = sv[j] * sc * w[j];
        __nv_bfloat16 hh = __float2bfloat16(v);
        nh[base + j] = hh;
        nl[base + j] = __float2bfloat16(v - __bfloat162float(hh));
    }
}

// ---------------- SwiGLU with bf16 hi/lo out (padded output stride) ----------------
__global__ void __launch_bounds__(256) swiglu_kernel(
    const float* __restrict__ g, const float* __restrict__ u,
    __nv_bfloat16* __restrict__ oh, __nv_bfloat16* __restrict__ ol,
    int rows, int cols, int ldo)
{
    int i = blockIdx.x * 256 + threadIdx.x;
    int total = rows * cols;
    if (i < total) {
        int r = i / cols;
        int c = i - r * cols;
        float x = g[i];
        float sig = 1.f / (1.f + __expf(-x));
        float v = x * sig * u[i];
        __nv_bfloat16 hh = __float2bfloat16(v);
        long o = (long)r * ldo + c;
        oh[o] = hh;
        ol[o] = __float2bfloat16(v - __bfloat162float(hh));
    }
}

// ---------------- fp32 -> bf16 hi/lo split (contiguous) ----------------
__global__ void __launch_bounds__(256) split_kernel(
    const float4* __restrict__ in, __nv_bfloat16* __restrict__ h,
    __nv_bfloat16* __restrict__ l, long n4)
{
    for (long i = (long)blockIdx.x * 256 + threadIdx.x; i < n4; i += (long)gridDim.x * 256) {
        float4 v = in[i];
        __nv_bfloat16 th[4], tl[4];
        float vv[4] = {v.x, v.y, v.z, v.w};
        #pragma unroll
        for (int j = 0; j < 4; j++) {
            th[j] = __float2bfloat16(vv[j]);
            tl[j] = __float2bfloat16(vv[j] - __bfloat162float(th[j]));
        }
        *reinterpret_cast<uint2*>(h + 4 * i) = *reinterpret_cast<uint2*>(th);
        *reinterpret_cast<uint2*>(l + 4 * i) = *reinterpret_cast<uint2*>(tl);
    }
}

// ---------------- fp32 -> bf16 hi/lo split with padded output stride ----------------
__global__ void __launch_bounds__(256) split_pad_kernel(
    const float* __restrict__ in, __nv_bfloat16* __restrict__ h,
    __nv_bfloat16* __restrict__ l, int rows, int cols, int ldo)
{
    int c4n = cols >> 2;
    long total = (long)rows * c4n;
    for (long i = (long)blockIdx.x * 256 + threadIdx.x; i < total; i += (long)gridDim.x * 256) {
        int r = (int)(i / c4n);
        int c4 = (int)(i - (long)r * c4n);
        float4 v = *reinterpret_cast<const float4*>(in + (long)r * cols + c4 * 4);
        __nv_bfloat16 th[4], tl[4];
        float vv[4] = {v.x, v.y, v.z, v.w};
        #pragma unroll
        for (int j = 0; j < 4; j++) {
            th[j] = __float2bfloat16(vv[j]);
            tl[j] = __float2bfloat16(vv[j] - __bfloat162float(th[j]));
        }
        long o = (long)r * ldo + c4 * 4;
        *reinterpret_cast<uint2*>(h + o) = *reinterpret_cast<uint2*>(th);
        *reinterpret_cast<uint2*>(l + o) = *reinterpret_cast<uint2*>(tl);
    }
}

// ---------------- host ----------------
static inline dim3 ggrid(int M, int N) { return dim3((N + 127) / 128, (M + 127) / 128); }

static inline void do_split(const float* src, __nv_bfloat16* h, __nv_bfloat16* l, long n) {
    long n4 = n / 4;
    int blocks = (int)((n4 + 255) / 256);
    if (blocks > 16384) blocks = 16384;
    split_kernel<<<blocks, 256>>>((const float4*)src, h, l, n4);
}
static inline void do_split_pad(const float* src, __nv_bfloat16* h, __nv_bfloat16* l,
                                int rows, int cols, int ldo) {
    long total = (long)rows * (cols / 4);
    int blocks = (int)((total + 255) / 256);
    if (blocks > 16384) blocks = 16384;
    split_pad_kernel<<<blocks, 256>>>(src, h, l, rows, cols, ldo);
}

extern "C" void kernel_launch(void* const* d_in, const int* in_sizes, int n_in,
                              void* d_out, int out_size)
{
    const float* x       = (const float*)d_in[0];
    const float* cosb    = (const float*)d_in[1];
    const float* sinb    = (const float*)d_in[2];
    const float* patch_w = (const float*)d_in[3];
    const float* norm1_w = (const float*)d_in[4];
    const float* norm2_w = (const float*)d_in[5];
    const float* qkv_w   = (const float*)d_in[6];
    const float* qkv_b   = (const float*)d_in[7];
    const float* proj_w  = (const float*)d_in[8];
    const float* proj_b  = (const float*)d_in[9];
    const float* gate_w  = (const float*)d_in[10];
    const float* gate_b  = (const float*)d_in[11];
    const float* up_w    = (const float*)d_in[12];
    const float* up_b    = (const float*)d_in[13];
    const float* down_w  = (const float*)d_in[14];
    const float* down_b  = (const float*)d_in[15];
    const float* lnq_w   = (const float*)d_in[16];
    const float* m0_w    = (const float*)d_in[17];
    const float* m0_b    = (const float*)d_in[18];
    const float* m2_w    = (const float*)d_in[19];
    const float* m2_b    = (const float*)d_in[20];

    float* fs = nullptr;
    __nv_bfloat16* bs = nullptr;
    cudaGetSymbolAddress((void**)&fs, g_f32);
    cudaGetSymbolAddress((void**)&bs, g_bf16);

    float* pX    = fs + F_X;
    float* pRES  = fs + F_RES;
    float* pHB   = fs + F_HB;
    float* pQKV  = fs + F_QKV;
    float* pGATE = fs + F_GATE;
    float* pUP   = fs + F_UP;

    __nv_bfloat16 *xH = bs+B_XH, *xL = bs+B_XL;
    __nv_bfloat16 *nH = bs+B_NH, *nL = bs+B_NL;
    __nv_bfloat16 *aH = bs+B_AH, *aL = bs+B_AL;
    __nv_bfloat16 *sH = bs+B_SH, *sL = bs+B_SL;
    __nv_bfloat16 *pwH = bs+B_PW,  *pwL = pwH + SZ_PW;
    __nv_bfloat16 *qwH = bs+B_QW,  *qwL = qwH + SZ_QW;
    __nv_bfloat16 *prH = bs+B_PRW, *prL = prH + SZ_PRW;
    __nv_bfloat16 *gwH = bs+B_GW,  *gwL = gwH + SZ_GWP;
    __nv_bfloat16 *uwH = bs+B_UW,  *uwL = uwH + SZ_GWP;
    __nv_bfloat16 *dwH = bs+B_DW,  *dwL = dwH + SZ_DW;
    __nv_bfloat16 *m0H = bs+B_M0W, *m0L = m0H + SZ_M0W;
    __nv_bfloat16 *m2H = bs+B_M2W, *m2L = m2H + SZ_M2W;

    cudaFuncSetAttribute(tcgemm_kernel<E_NONE>, cudaFuncAttributeMaxDynamicSharedMemorySize, GEMM_SMEM);
    cudaFuncSetAttribute(tcgemm_kernel<E_BIAS>, cudaFuncAttributeMaxDynamicSharedMemorySize, GEMM_SMEM);
    cudaFuncSetAttribute(tcgemm_kernel<E_BIAS_RES>, cudaFuncAttributeMaxDynamicSharedMemorySize, GEMM_SMEM);
    cudaFuncSetAttribute(tcgemm_kernel<E_GELU_SPLIT>, cudaFuncAttributeMaxDynamicSharedMemorySize, GEMM_SMEM);
    cudaFuncSetAttribute(attn_kernel, cudaFuncAttributeMaxDynamicSharedMemorySize, ATTN_SMEM);

    // weight + input splits (padded for the 3420-wide matrices)
    do_split(patch_w, pwH, pwL, SZ_PW);
    do_split(qkv_w,   qwH, qwL, SZ_QW);
    do_split(proj_w,  prH, prL, SZ_PRW);
    do_split_pad(gate_w, gwH, gwL, NBLK * HDIM, MHID, MH_P);
    do_split_pad(up_w,   uwH, uwL, NBLK * HDIM, MHID, MH_P);
    do_split(down_w,  dwH, dwL, SZ_DW);
    do_split(m0_w,    m0H, m0L, SZ_M0W);
    do_split(m2_w,    m2H, m2L, SZ_M2W);
    do_split(x,       xH,  xL,  SZ_XS);

    cudaMemsetAsync(pRES, 0, SZ_LH * sizeof(float));

    // patch embed: [8192,1176]@[1176,1280]
    tcgemm_kernel<E_NONE><<<ggrid(LTOK, HDIM), GT, GEMM_SMEM>>>(
        xH, xL, pwH, pwL, nullptr, nullptr, pX, nullptr, nullptr,
        LTOK, HDIM, PDIM, PDIM, HDIM, HDIM);

    for (int d = 0; d < NBLK; d++) {
        rmsnorm_kernel<<<LTOK, 256>>>(pX, pRES, norm1_w + (long)d * HDIM, pHB, nH, nL);
        tcgemm_kernel<E_BIAS><<<ggrid(LTOK, 3 * HDIM), GT, GEMM_SMEM>>>(
            nH, nL, qwH + (long)d * HDIM * 3 * HDIM, qwL + (long)d * HDIM * 3 * HDIM,
            qkv_b + (long)d * 3 * HDIM, nullptr, pQKV, nullptr, nullptr,
            LTOK, 3 * HDIM, HDIM, HDIM, 3 * HDIM, 3 * HDIM);
        attn_kernel<<<NWIN * NHEAD, 256, ATTN_SMEM>>>(pQKV, cosb, sinb, aH, aL);
        tcgemm_kernel<E_BIAS_RES><<<ggrid(LTOK, HDIM), GT, GEMM_SMEM>>>(
            aH, aL, prH + (long)d * HDIM * HDIM, prL + (long)d * HDIM * HDIM,
            proj_b + (long)d * HDIM, pHB, pRES, nullptr, nullptr,
            LTOK, HDIM, HDIM, HDIM, HDIM, HDIM);
        rmsnorm_kernel<<<LTOK, 256>>>(pRES, nullptr, norm2_w + (long)d * HDIM, nullptr, nH, nL);
        tcgemm_kernel<E_BIAS><<<ggrid(LTOK, MHID), GT, GEMM_SMEM>>>(
            nH, nL, gwH + (long)d * HDIM * MH_P, gwL + (long)d * HDIM * MH_P,
            gate_b + (long)d * MHID, nullptr, pGATE, nullptr, nullptr,
            LTOK, MHID, HDIM, HDIM, MH_P, MHID);
        tcgemm_kernel<E_BIAS><<<ggrid(LTOK, MHID), GT, GEMM_SMEM>>>(
            nH, nL, uwH + (long)d * HDIM * MH_P, uwL + (long)d * HDIM * MH_P,
            up_b + (long)d * MHID, nullptr, pUP, nullptr, nullptr,
            LTOK, MHID, HDIM, HDIM, MH_P, MHID);
        swiglu_kernel<<<(unsigned)(((long)LTOK * MHID + 255) / 256), 256>>>(
            pGATE, pUP, sH, sL, LTOK, MHID, MH_P);
        tcgemm_kernel<E_BIAS><<<ggrid(LTOK, HDIM), GT, GEMM_SMEM>>>(
            sH, sL, dwH + (long)d * MHID * HDIM, dwL + (long)d * MHID * HDIM,
            down_b + (long)d * HDIM, nullptr, pX, nullptr, nullptr,
            LTOK, HDIM, MHID, MH_P, HDIM, HDIM);
    }

    // merger
    rmsnorm_kernel<<<LTOK, 256>>>(pX, pRES, lnq_w, nullptr, nH, nL);
    tcgemm_kernel<E_GELU_SPLIT><<<ggrid(LMERG, H4), GT, GEMM_SMEM>>>(
        nH, nL, m0H, m0L, m0_b, nullptr, nullptr, aH, aL,
        LMERG, H4, H4, H4, H4, H4);
    tcgemm_kernel<E_BIAS><<<ggrid(LMERG, DMODEL), GT, GEMM_SMEM>>>(
        aH, aL, m2H, m2L, m2_b, nullptr, (float*)d_out, nullptr, nullptr,
        LMERG, DMODEL, H4, H4, DMODEL, DMODEL);
}

// round 6
// speedup vs baseline: 1.0094x; 1.0094x over previous
#include <cuda_runtime.h>
#include <cuda_bf16.h>
#include <math.h>
#include <stdint.h>

// ---------------- problem constants ----------------
#define LTOK 8192
#define HDIM 1280
#define NHEAD 16
#define HEADD 80
#define MHID 3420
#define MH_P 3424          // padded leading dim (16B-aligned bf16 rows)
#define NBLK 4
#define NWIN 128
#define PDIM 1176
#define DMODEL 3584
#define H4 5120
#define LMERG 2048

// ---------------- fp32 scratch ----------------
static constexpr long SZ_LH  = (long)LTOK * HDIM;
static constexpr long SZ_L3H = (long)LTOK * 3 * HDIM;
static constexpr long SZ_LMH = (long)LTOK * MHID;

static constexpr long F_X    = 0;
static constexpr long F_RES  = F_X   + SZ_LH;
static constexpr long F_HB   = F_RES + SZ_LH;
static constexpr long F_QKV  = F_HB  + SZ_LH;
static constexpr long F_GATE = F_QKV + SZ_L3H;
static constexpr long F_UP   = F_GATE + SZ_LMH;
static constexpr long F_TOTAL = F_UP + SZ_LMH;
__device__ float g_f32[F_TOTAL];

// ---------------- bf16 scratch (hi/lo pairs) ----------------
static constexpr long SZ_XS  = (long)LTOK * PDIM;
static constexpr long SZ_PW  = (long)PDIM * HDIM;
static constexpr long SZ_QW  = (long)NBLK * HDIM * 3*HDIM;
static constexpr long SZ_PRW = (long)NBLK * HDIM * HDIM;
static constexpr long SZ_GWP = (long)NBLK * HDIM * MH_P;   // padded
static constexpr long SZ_DW  = (long)NBLK * MHID * HDIM;
static constexpr long SZ_M0W = (long)H4 * H4;
static constexpr long SZ_M2W = (long)H4 * DMODEL;
static constexpr long SZ_SHP = (long)LTOK * MH_P;          // padded swiglu out

static constexpr long B_XH  = 0;
static constexpr long B_XL  = B_XH + SZ_XS;
static constexpr long B_NH  = B_XL + SZ_XS;
static constexpr long B_NL  = B_NH + SZ_LH;
static constexpr long B_AH  = B_NL + SZ_LH;
static constexpr long B_AL  = B_AH + SZ_LH;
static constexpr long B_SH  = B_AL + SZ_LH;
static constexpr long B_SL  = B_SH + SZ_SHP;
static constexpr long B_PW  = B_SL + SZ_SHP;
static constexpr long B_QW  = B_PW + 2*SZ_PW;
static constexpr long B_PRW = B_QW + 2*SZ_QW;
static constexpr long B_GW  = B_PRW + 2*SZ_PRW;
static constexpr long B_UW  = B_GW + 2*SZ_GWP;
static constexpr long B_DW  = B_UW + 2*SZ_GWP;
static constexpr long B_M0W = B_DW + 2*SZ_DW;
static constexpr long B_M2W = B_M0W + 2*SZ_M0W;
static constexpr long B_TOTAL = B_M2W + 2*SZ_M2W;
__device__ __nv_bfloat16 g_bf16[B_TOTAL];

// ---------------- PTX helpers (base sm_103 target only!) ----------------
__device__ __forceinline__ uint32_t smem_to_u32(const void* p) {
    uint32_t a;
    asm("{ .reg .u64 t; cvta.to.shared.u64 t, %1; cvt.u32.u64 %0, t; }" : "=r"(a) : "l"(p));
    return a;
}
__device__ __forceinline__ void cp16(uint32_t dst, const void* src, int bytes) {
    asm volatile("cp.async.cg.shared.global [%0], [%1], 16, %2;"
                 :: "r"(dst), "l"(src), "r"(bytes));
}
#define CP_COMMIT() asm volatile("cp.async.commit_group;" ::: "memory")
#define CP_WAIT2()  asm volatile("cp.async.wait_group 2;" ::: "memory")

__device__ __forceinline__ void ldsm_x4(uint32_t r[4], uint32_t addr) {
    asm volatile("ldmatrix.sync.aligned.m8n8.x4.shared.b16 {%0,%1,%2,%3}, [%4];"
                 : "=r"(r[0]), "=r"(r[1]), "=r"(r[2]), "=r"(r[3]) : "r"(addr));
}
__device__ __forceinline__ void ldsm_x4t(uint32_t r[4], uint32_t addr) {
    asm volatile("ldmatrix.sync.aligned.m8n8.x4.trans.shared.b16 {%0,%1,%2,%3}, [%4];"
                 : "=r"(r[0]), "=r"(r[1]), "=r"(r[2]), "=r"(r[3]) : "r"(addr));
}
__device__ __forceinline__ void mma_bf16(float c[4], const uint32_t a[4],
                                         uint32_t b0, uint32_t b1) {
    asm volatile(
        "mma.sync.aligned.m16n8k16.row.col.f32.bf16.bf16.f32 "
        "{%0,%1,%2,%3}, {%4,%5,%6,%7}, {%8,%9}, {%0,%1,%2,%3};"
        : "+f"(c[0]), "+f"(c[1]), "+f"(c[2]), "+f"(c[3])
        : "r"(a[0]), "r"(a[1]), "r"(a[2]), "r"(a[3]), "r"(b0), "r"(b1));
}

// ---------------- tensor-core GEMM (bf16x3 split, fp32 accum) ----------------
enum { E_NONE = 0, E_BIAS = 1, E_BIAS_RES = 2, E_GELU_SPLIT = 3 };

// Tiles: BM=128, BN=256, BK=32. 8 warps in 2(M)x4(N); warp tile 64x64.
#define A_STRIDE 40
#define B_STRIDE 264
#define A_TILE_B (128 * A_STRIDE * 2)      // 10240
#define B_TILE_B (32 * B_STRIDE * 2)       // 16896
#define STAGE_B  (2 * A_TILE_B + 2 * B_TILE_B)  // 54272
#define OFF_AH 0
#define OFF_AL A_TILE_B
#define OFF_BH (2 * A_TILE_B)
#define OFF_BL (2 * A_TILE_B + B_TILE_B)
#define GEMM_SMEM (3 * STAGE_B)            // 162816
#define GT 256                             // GEMM threads

template<int EPI>
__global__ void __launch_bounds__(GT, 1) tcgemm_kernel(
    const __nv_bfloat16* __restrict__ Ah, const __nv_bfloat16* __restrict__ Al,
    const __nv_bfloat16* __restrict__ Bh, const __nv_bfloat16* __restrict__ Bl,
    const float* __restrict__ bias, const float* __restrict__ res,
    float* __restrict__ C, __nv_bfloat16* __restrict__ Oh, __nv_bfloat16* __restrict__ Ol,
    int M, int N, int K, int lda, int ldb, int ldc)
{
    extern __shared__ __align__(16) char sm[];
    const uint32_t smem_u = smem_to_u32(sm);
    const int tid = threadIdx.x;
    const int lane = tid & 31, wid = tid >> 5;
    const int wm = wid >> 2, wn = wid & 3;        // 2(M) x 4(N) warp grid
    const int row0 = blockIdx.y * 128, col0 = blockIdx.x * 256;

    const int nc = (K + 31) / 32;

    // -------- stage loader --------
    auto load_stage = [&](int st, int c) {
        const uint32_t sbase = smem_u + st * STAGE_B;
        const int k0 = c * 32;
        // A tiles: 128 rows x 32 bf16 (4 x 16B per row); 512 vecs per half
        #pragma unroll
        for (int h = 0; h < 2; ++h) {
            const __nv_bfloat16* src = h ? Al : Ah;
            const uint32_t dbase = sbase + (h ? OFF_AL : OFF_AH);
            #pragma unroll
            for (int it = 0; it < 2; ++it) {
                int e = tid + it * 256;
                int r = e >> 2, q = e & 3;
                int gr = row0 + r;
                int gk = k0 + q * 8;
                int bytes = (K - gk) * 2;
                bytes = bytes < 0 ? 0 : (bytes > 16 ? 16 : bytes);
                const __nv_bfloat16* g = src + (long)gr * lda + (bytes > 0 ? gk : 0);
                cp16(dbase + r * (A_STRIDE * 2) + q * 16, g, bytes);
            }
        }
        // B tiles: 32 rows x 256 bf16 (32 x 16B per row); 1024 vecs per half
        #pragma unroll
        for (int h = 0; h < 2; ++h) {
            const __nv_bfloat16* src = h ? Bl : Bh;
            const uint32_t dbase = sbase + (h ? OFF_BL : OFF_BH);
            #pragma unroll
            for (int it = 0; it < 4; ++it) {
                int e = tid + it * 256;
                int r = e >> 5, q = e & 31;
                int gk = k0 + r;
                int gc = col0 + q * 8;
                int bytes = (N - gc) * 2;
                bytes = bytes < 0 ? 0 : (bytes > 16 ? 16 : bytes);
                if (gk >= K) bytes = 0;
                const __nv_bfloat16* g = src + (long)(gk < K ? gk : 0) * ldb + (bytes > 0 ? gc : 0);
                cp16(dbase + r * (B_STRIDE * 2) + q * 16, g, bytes);
            }
        }
    };

    // -------- ldmatrix lane offsets --------
    const int a_row = lane & 15;
    const int a_kh = (lane >> 4) * 8;
    const int b_g = lane >> 3, b_l = lane & 7;
    const int b_k = (b_g & 1) * 8 + b_l;
    const int b_n = (b_g >> 1) * 8;

    float acc[4][8][4];
    #pragma unroll
    for (int i = 0; i < 4; ++i)
        #pragma unroll
        for (int j = 0; j < 8; ++j)
            #pragma unroll
            for (int r = 0; r < 4; ++r) acc[i][j][r] = 0.f;

    // prologue
    #pragma unroll
    for (int s = 0; s < 3; ++s) {
        if (s < nc) load_stage(s, s);
        CP_COMMIT();
    }

    for (int c = 0; c < nc; ++c) {
        CP_WAIT2();
        __syncthreads();
        const int st = c % 3;
        const uint32_t sbase = smem_u + st * STAGE_B;
        const uint32_t aB[2] = { sbase + OFF_AH, sbase + OFF_AL };
        const uint32_t bB[2] = { sbase + OFF_BH, sbase + OFF_BL };

        #pragma unroll
        for (int ks = 0; ks < 2; ++ks) {
            uint32_t af[2][4][4];
            #pragma unroll
            for (int h = 0; h < 2; ++h)
                #pragma unroll
                for (int i = 0; i < 4; ++i)
                    ldsm_x4(af[h][i],
                        aB[h] + 2u * ((wm * 64 + i * 16 + a_row) * A_STRIDE + ks * 16 + a_kh));
            // stream B fragments per 16-column block
            #pragma unroll
            for (int j2 = 0; j2 < 4; ++j2) {
                uint32_t b0[4], b1[4];
                uint32_t boff = 2u * ((ks * 16 + b_k) * B_STRIDE + wn * 64 + j2 * 16 + b_n);
                ldsm_x4t(b0, bB[0] + boff);
                ldsm_x4t(b1, bB[1] + boff);
                // combo Ah*Bh
                #pragma unroll
                for (int i = 0; i < 4; ++i) {
                    mma_bf16(acc[i][2*j2],   af[0][i], b0[0], b0[1]);
                    mma_bf16(acc[i][2*j2+1], af[0][i], b0[2], b0[3]);
                }
                // combo Ah*Bl
                #pragma unroll
                for (int i = 0; i < 4; ++i) {
                    mma_bf16(acc[i][2*j2],   af[0][i], b1[0], b1[1]);
                    mma_bf16(acc[i][2*j2+1], af[0][i], b1[2], b1[3]);
                }
                // combo Al*Bh
                #pragma unroll
                for (int i = 0; i < 4; ++i) {
                    mma_bf16(acc[i][2*j2],   af[1][i], b0[0], b0[1]);
                    mma_bf16(acc[i][2*j2+1], af[1][i], b0[2], b0[3]);
                }
            }
        }
        __syncthreads();
        if (c + 3 < nc) load_stage(st, c + 3);
        CP_COMMIT();
    }

    // -------- epilogue --------
    const int g = lane >> 2, t = lane & 3;
    #pragma unroll
    for (int i = 0; i < 4; ++i) {
        #pragma unroll
        for (int j = 0; j < 8; ++j) {
            int col = col0 + wn * 64 + j * 8 + t * 2;
            if (col >= N) continue;
            float b0 = 0.f, b1 = 0.f;
            if (EPI != E_NONE) { b0 = bias[col]; b1 = bias[col + 1]; }
            #pragma unroll
            for (int rr = 0; rr < 2; ++rr) {
                int row = row0 + wm * 64 + i * 16 + g + rr * 8;
                if (row >= M) continue;
                float v0 = acc[i][j][rr * 2 + 0] + b0;
                float v1 = acc[i][j][rr * 2 + 1] + b1;
                long idx = (long)row * ldc + col;
                if (EPI == E_BIAS_RES) { v0 += res[idx]; v1 += res[idx + 1]; }
                if (EPI == E_GELU_SPLIT) {
                    v0 = 0.5f * v0 * (1.f + erff(v0 * 0.70710678118654752f));
                    v1 = 0.5f * v1 * (1.f + erff(v1 * 0.70710678118654752f));
                    __nv_bfloat16 h0 = __float2bfloat16(v0);
                    __nv_bfloat16 h1 = __float2bfloat16(v1);
                    Oh[idx] = h0; Oh[idx + 1] = h1;
                    Ol[idx]     = __float2bfloat16(v0 - __bfloat162float(h0));
                    Ol[idx + 1] = __float2bfloat16(v1 - __bfloat162float(h1));
                } else {
                    float2 o = make_float2(v0, v1);
                    *reinterpret_cast<float2*>(C + idx) = o;
                }
            }
        }
    }
}

// ---------------- fused windowed attention with inline RoPE (fp32) ----------------
#define SP 81
#define ATTN_SMEM ((3 * 64 * SP + 64 * 64) * 4)

__global__ void __launch_bounds__(256) attn_kernel(
    const float* __restrict__ qkv, const float* __restrict__ cosb,
    const float* __restrict__ sinb, __nv_bfloat16* __restrict__ outH,
    __nv_bfloat16* __restrict__ outL)
{
    extern __shared__ float smf[];
    float* q = smf;
    float* k = smf + 64 * SP;
    float* v = smf + 2 * 64 * SP;
    float* s = smf + 3 * 64 * SP;

    const int w = blockIdx.x >> 4;
    const int h = blockIdx.x & 15;
    const int tid = threadIdx.x;
    const float scale = 0.11180339887498949f;

    for (int e = tid; e < 64 * 80; e += 256) {
        int t = e / 80, j = e % 80;
        int l = w * 64 + t;
        long base = (long)l * (3 * HDIM) + h * 80;
        float c = cosb[l * 80 + j], sn = sinb[l * 80 + j];
        float qv = qkv[base + j];
        float qr = (j < 40) ? -qkv[base + j + 40] : qkv[base + j - 40];
        q[t * SP + j] = qv * c + qr * sn;
        float kv = qkv[base + HDIM + j];
        float kr = (j < 40) ? -qkv[base + HDIM + j + 40] : qkv[base + HDIM + j - 40];
        k[t * SP + j] = kv * c + kr * sn;
        v[t * SP + j] = qkv[base + 2 * HDIM + j];
    }
    __syncthreads();

    {
        const int tx = tid & 15, ty = tid >> 4;
        float acc[4][4] = {};
        for (int d = 0; d < 80; d++) {
            float qa[4], kb[4];
            #pragma unroll
            for (int i = 0; i < 4; i++) qa[i] = q[(ty * 4 + i) * SP + d];
            #pragma unroll
            for (int j = 0; j < 4; j++) kb[j] = k[(tx * 4 + j) * SP + d];
            #pragma unroll
            for (int i = 0; i < 4; i++)
                #pragma unroll
                for (int j = 0; j < 4; j++)
                    acc[i][j] += qa[i] * kb[j];
        }
        #pragma unroll
        for (int i = 0; i < 4; i++)
            #pragma unroll
            for (int j = 0; j < 4; j++)
                s[(ty * 4 + i) * 64 + tx * 4 + j] = acc[i][j] * scale;
    }
    __syncthreads();

    {
        const int warp = tid >> 5, lane = tid & 31;
        for (int r = warp; r < 64; r += 8) {
            float x0 = s[r * 64 + lane], x1 = s[r * 64 + 32 + lane];
            float mx = fmaxf(x0, x1);
            #pragma unroll
            for (int o = 16; o > 0; o >>= 1) mx = fmaxf(mx, __shfl_xor_sync(~0u, mx, o));
            float e0 = __expf(x0 - mx), e1 = __expf(x1 - mx);
            float sum = e0 + e1;
            #pragma unroll
            for (int o = 16; o > 0; o >>= 1) sum += __shfl_xor_sync(~0u, sum, o);
            float inv = 1.f / sum;
            s[r * 64 + lane] = e0 * inv;
            s[r * 64 + 32 + lane] = e1 * inv;
        }
    }
    __syncthreads();

    {
        const int tx = tid & 15, ty = tid >> 4;
        float acc[4][5] = {};
        for (int kk = 0; kk < 64; kk++) {
            float sa[4], vb[5];
            #pragma unroll
            for (int i = 0; i < 4; i++) sa[i] = s[(ty * 4 + i) * 64 + kk];
            #pragma unroll
            for (int j = 0; j < 5; j++) vb[j] = v[kk * SP + tx * 5 + j];
            #pragma unroll
            for (int i = 0; i < 4; i++)
                #pragma unroll
                for (int j = 0; j < 5; j++)
                    acc[i][j] += sa[i] * vb[j];
        }
        #pragma unroll
        for (int i = 0; i < 4; i++) {
            long obase = (long)(w * 64 + ty * 4 + i) * HDIM + h * 80 + tx * 5;
            #pragma unroll
            for (int j = 0; j < 5; j++) {
                float val = acc[i][j];
                __nv_bfloat16 hh = __float2bfloat16(val);
                outH[obase + j] = hh;
                outL[obase + j] = __float2bfloat16(val - __bfloat162float(hh));
            }
        }
    }
}

// ---------------- fused (optional add) + RMSNorm, bf16 hi/lo out ----------------
__global__ void __launch_bounds__(256) rmsnorm_kernel(
    const float* __restrict__ a, const float* __restrict__ b,
    const float* __restrict__ w, float* __restrict__ sum_out,
    __nv_bfloat16* __restrict__ nh, __nv_bfloat16* __restrict__ nl)
{
    __shared__ float sv[HDIM];
    __shared__ float red[8];
    __shared__ float s_scale;
    const int row = blockIdx.x, tid = threadIdx.x;
    const long base = (long)row * HDIM;
    float ss = 0.f;
    for (int j = tid; j < HDIM; j += 256) {
        float v = a[base + j];
        if (b) v += b[base + j];
        sv[j] = v;
        if (sum_out) sum_out[base + j] = v;
        ss += v * v;
    }
    #pragma unroll
    for (int o = 16; o > 0; o >>= 1) ss += __shfl_xor_sync(~0u, ss, o);
    if ((tid & 31) == 0) red[tid >> 5] = ss;
    __syncthreads();
    if (tid == 0) {
        float t = 0.f;
        #pragma unroll
        for (int i = 0; i < 8; i++) t += red[i];
        s_scale = rsqrtf(t / (float)HDIM + 1e-6f);
    }
    __syncthreads();
    float sc = s_scale;
    for (int j = tid; j < HDIM; j += 256) {
        float v = sv[j] * sc * w[j];
        __nv_bfloat16 hh = __float2bfloat16(v);
        nh[base + j] = hh;
        nl[base + j] = __float2bfloat16(v - __bfloat162float(hh));
    }
}

// ---------------- SwiGLU with bf16 hi/lo out (padded output stride) ----------------
__global__ void __launch_bounds__(256) swiglu_kernel(
    const float* __restrict__ g, const float* __restrict__ u,
    __nv_bfloat16* __restrict__ oh, __nv_bfloat16* __restrict__ ol,
    int rows, int cols, int ldo)
{
    int i = blockIdx.x * 256 + threadIdx.x;
    int total = rows * cols;
    if (i < total) {
        int r = i / cols;
        int c = i - r * cols;
        float x = g[i];
        float sig = 1.f / (1.f + __expf(-x));
        float v = x * sig * u[i];
        __nv_bfloat16 hh = __float2bfloat16(v);
        long o = (long)r * ldo + c;
        oh[o] = hh;
        ol[o] = __float2bfloat16(v - __bfloat162float(hh));
    }
}

// ---------------- fp32 -> bf16 hi/lo split (contiguous) ----------------
__global__ void __launch_bounds__(256) split_kernel(
    const float4* __restrict__ in, __nv_bfloat16* __restrict__ h,
    __nv_bfloat16* __restrict__ l, long n4)
{
    for (long i = (long)blockIdx.x * 256 + threadIdx.x; i < n4; i += (long)gridDim.x * 256) {
        float4 v = in[i];
        __nv_bfloat16 th[4], tl[4];
        float vv[4] = {v.x, v.y, v.z, v.w};
        #pragma unroll
        for (int j = 0; j < 4; j++) {
            th[j] = __float2bfloat16(vv[j]);
            tl[j] = __float2bfloat16(vv[j] - __bfloat162float(th[j]));
        }
        *reinterpret_cast<uint2*>(h + 4 * i) = *reinterpret_cast<uint2*>(th);
        *reinterpret_cast<uint2*>(l + 4 * i) = *reinterpret_cast<uint2*>(tl);
    }
}

// ---------------- fp32 -> bf16 hi/lo split with padded output stride ----------------
__global__ void __launch_bounds__(256) split_pad_kernel(
    const float* __restrict__ in, __nv_bfloat16* __restrict__ h,
    __nv_bfloat16* __restrict__ l, int rows, int cols, int ldo)
{
    int c4n = cols >> 2;
    long total = (long)rows * c4n;
    for (long i = (long)blockIdx.x * 256 + threadIdx.x; i < total; i += (long)gridDim.x * 256) {
        int r = (int)(i / c4n);
        int c4 = (int)(i - (long)r * c4n);
        float4 v = *reinterpret_cast<const float4*>(in + (long)r * cols + c4 * 4);
        __nv_bfloat16 th[4], tl[4];
        float vv[4] = {v.x, v.y, v.z, v.w};
        #pragma unroll
        for (int j = 0; j < 4; j++) {
            th[j] = __float2bfloat16(vv[j]);
            tl[j] = __float2bfloat16(vv[j] - __bfloat162float(th[j]));
        }
        long o = (long)r * ldo + c4 * 4;
        *reinterpret_cast<uint2*>(h + o) = *reinterpret_cast<uint2*>(th);
        *reinterpret_cast<uint2*>(l + o) = *reinterpret_cast<uint2*>(tl);
    }
}

// ---------------- host ----------------
static inline dim3 ggrid(int M, int N) { return dim3((N + 255) / 256, (M + 127) / 128); }

static inline void do_split(const float* src, __nv_bfloat16* h, __nv_bfloat16* l, long n) {
    long n4 = n / 4;
    int blocks = (int)((n4 + 255) / 256);
    if (blocks > 16384) blocks = 16384;
    split_kernel<<<blocks, 256>>>((const float4*)src, h, l, n4);
}
static inline void do_split_pad(const float* src, __nv_bfloat16* h, __nv_bfloat16* l,
                                int rows, int cols, int ldo) {
    long total = (long)rows * (cols / 4);
    int blocks = (int)((total + 255) / 256);
    if (blocks > 16384) blocks = 16384;
    split_pad_kernel<<<blocks, 256>>>(src, h, l, rows, cols, ldo);
}

extern "C" void kernel_launch(void* const* d_in, const int* in_sizes, int n_in,
                              void* d_out, int out_size)
{
    const float* x       = (const float*)d_in[0];
    const float* cosb    = (const float*)d_in[1];
    const float* sinb    = (const float*)d_in[2];
    const float* patch_w = (const float*)d_in[3];
    const float* norm1_w = (const float*)d_in[4];
    const float* norm2_w = (const float*)d_in[5];
    const float* qkv_w   = (const float*)d_in[6];
    const float* qkv_b   = (const float*)d_in[7];
    const float* proj_w  = (const float*)d_in[8];
    const float* proj_b  = (const float*)d_in[9];
    const float* gate_w  = (const float*)d_in[10];
    const float* gate_b  = (const float*)d_in[11];
    const float* up_w    = (const float*)d_in[12];
    const float* up_b    = (const float*)d_in[13];
    const float* down_w  = (const float*)d_in[14];
    const float* down_b  = (const float*)d_in[15];
    const float* lnq_w   = (const float*)d_in[16];
    const float* m0_w    = (const float*)d_in[17];
    const float* m0_b    = (const float*)d_in[18];
    const float* m2_w    = (const float*)d_in[19];
    const float* m2_b    = (const float*)d_in[20];

    float* fs = nullptr;
    __nv_bfloat16* bs = nullptr;
    cudaGetSymbolAddress((void**)&fs, g_f32);
    cudaGetSymbolAddress((void**)&bs, g_bf16);

    float* pX    = fs + F_X;
    float* pRES  = fs + F_RES;
    float* pHB   = fs + F_HB;
    float* pQKV  = fs + F_QKV;
    float* pGATE = fs + F_GATE;
    float* pUP   = fs + F_UP;

    __nv_bfloat16 *xH = bs+B_XH, *xL = bs+B_XL;
    __nv_bfloat16 *nH = bs+B_NH, *nL = bs+B_NL;
    __nv_bfloat16 *aH = bs+B_AH, *aL = bs+B_AL;
    __nv_bfloat16 *sH = bs+B_SH, *sL = bs+B_SL;
    __nv_bfloat16 *pwH = bs+B_PW,  *pwL = pwH + SZ_PW;
    __nv_bfloat16 *qwH = bs+B_QW,  *qwL = qwH + SZ_QW;
    __nv_bfloat16 *prH = bs+B_PRW, *prL = prH + SZ_PRW;
    __nv_bfloat16 *gwH = bs+B_GW,  *gwL = gwH + SZ_GWP;
    __nv_bfloat16 *uwH = bs+B_UW,  *uwL = uwH + SZ_GWP;
    __nv_bfloat16 *dwH = bs+B_DW,  *dwL = dwH + SZ_DW;
    __nv_bfloat16 *m0H = bs+B_M0W, *m0L = m0H + SZ_M0W;
    __nv_bfloat16 *m2H = bs+B_M2W, *m2L = m2H + SZ_M2W;

    cudaFuncSetAttribute(tcgemm_kernel<E_NONE>, cudaFuncAttributeMaxDynamicSharedMemorySize, GEMM_SMEM);
    cudaFuncSetAttribute(tcgemm_kernel<E_BIAS>, cudaFuncAttributeMaxDynamicSharedMemorySize, GEMM_SMEM);
    cudaFuncSetAttribute(tcgemm_kernel<E_BIAS_RES>, cudaFuncAttributeMaxDynamicSharedMemorySize, GEMM_SMEM);
    cudaFuncSetAttribute(tcgemm_kernel<E_GELU_SPLIT>, cudaFuncAttributeMaxDynamicSharedMemorySize, GEMM_SMEM);
    cudaFuncSetAttribute(attn_kernel, cudaFuncAttributeMaxDynamicSharedMemorySize, ATTN_SMEM);

    // weight + input splits (padded for the 3420-wide matrices)
    do_split(patch_w, pwH, pwL, SZ_PW);
    do_split(qkv_w,   qwH, qwL, SZ_QW);
    do_split(proj_w,  prH, prL, SZ_PRW);
    do_split_pad(gate_w, gwH, gwL, NBLK * HDIM, MHID, MH_P);
    do_split_pad(up_w,   uwH, uwL, NBLK * HDIM, MHID, MH_P);
    do_split(down_w,  dwH, dwL, SZ_DW);
    do_split(m0_w,    m0H, m0L, SZ_M0W);
    do_split(m2_w,    m2H, m2L, SZ_M2W);
    do_split(x,       xH,  xL,  SZ_XS);

    cudaMemsetAsync(pRES, 0, SZ_LH * sizeof(float));

    // patch embed: [8192,1176]@[1176,1280]
    tcgemm_kernel<E_NONE><<<ggrid(LTOK, HDIM), GT, GEMM_SMEM>>>(
        xH, xL, pwH, pwL, nullptr, nullptr, pX, nullptr, nullptr,
        LTOK, HDIM, PDIM, PDIM, HDIM, HDIM);

    for (int d = 0; d < NBLK; d++) {
        rmsnorm_kernel<<<LTOK, 256>>>(pX, pRES, norm1_w + (long)d * HDIM, pHB, nH, nL);
        tcgemm_kernel<E_BIAS><<<ggrid(LTOK, 3 * HDIM), GT, GEMM_SMEM>>>(
            nH, nL, qwH + (long)d * HDIM * 3 * HDIM, qwL + (long)d * HDIM * 3 * HDIM,
            qkv_b + (long)d * 3 * HDIM, nullptr, pQKV, nullptr, nullptr,
            LTOK, 3 * HDIM, HDIM, HDIM, 3 * HDIM, 3 * HDIM);
        attn_kernel<<<NWIN * NHEAD, 256, ATTN_SMEM>>>(pQKV, cosb, sinb, aH, aL);
        tcgemm_kernel<E_BIAS_RES><<<ggrid(LTOK, HDIM), GT, GEMM_SMEM>>>(
            aH, aL, prH + (long)d * HDIM * HDIM, prL + (long)d * HDIM * HDIM,
            proj_b + (long)d * HDIM, pHB, pRES, nullptr, nullptr,
            LTOK, HDIM, HDIM, HDIM, HDIM, HDIM);
        rmsnorm_kernel<<<LTOK, 256>>>(pRES, nullptr, norm2_w + (long)d * HDIM, nullptr, nH, nL);
        tcgemm_kernel<E_BIAS><<<ggrid(LTOK, MHID), GT, GEMM_SMEM>>>(
            nH, nL, gwH + (long)d * HDIM * MH_P, gwL + (long)d * HDIM * MH_P,
            gate_b + (long)d * MHID, nullptr, pGATE, nullptr, nullptr,
            LTOK, MHID, HDIM, HDIM, MH_P, MHID);
        tcgemm_kernel<E_BIAS><<<ggrid(LTOK, MHID), GT, GEMM_SMEM>>>(
            nH, nL, uwH + (long)d * HDIM * MH_P, uwL + (long)d * HDIM * MH_P,
            up_b + (long)d * MHID, nullptr, pUP, nullptr, nullptr,
            LTOK, MHID, HDIM, HDIM, MH_P, MHID);
        swiglu_kernel<<<(unsigned)(((long)LTOK * MHID + 255) / 256), 256>>>(
            pGATE, pUP, sH, sL, LTOK, MHID, MH_P);
        tcgemm_kernel<E_BIAS><<<ggrid(LTOK, HDIM), GT, GEMM_SMEM>>>(
            sH, sL, dwH + (long)d * MHID * HDIM, dwL + (long)d * MHID * HDIM,
            down_b + (long)d * HDIM, nullptr, pX, nullptr, nullptr,
            LTOK, HDIM, MHID, MH_P, HDIM, HDIM);
    }

    // merger
    rmsnorm_kernel<<<LTOK, 256>>>(pX, pRES, lnq_w, nullptr, nH, nL);
    tcgemm_kernel<E_GELU_SPLIT><<<ggrid(LMERG, H4), GT, GEMM_SMEM>>>(
        nH, nL, m0H, m0L, m0_b, nullptr, nullptr, aH, aL,
        LMERG, H4, H4, H4, H4, H4);
    tcgemm_kernel<E_BIAS><<<ggrid(LMERG, DMODEL), GT, GEMM_SMEM>>>(
        aH, aL, m2H, m2L, m2_b, nullptr, (float*)d_out, nullptr, nullptr,
        LMERG, DMODEL, H4, H4, DMODEL, DMODEL);
}

// round 7
// speedup vs baseline: 1.1709x; 1.1600x over previous
#include <cuda_runtime.h>
#include <cuda_bf16.h>
#include <math.h>
#include <stdint.h>

// ---------------- problem constants ----------------
#define LTOK 8192
#define HDIM 1280
#define NHEAD 16
#define HEADD 80
#define MHID 3420
#define MH_P 3424          // padded leading dim (16B-aligned bf16 rows)
#define NBLK 4
#define NWIN 128
#define PDIM 1176
#define DMODEL 3584
#define H4 5120
#define LMERG 2048

// ---------------- fp32 scratch ----------------
static constexpr long SZ_LH  = (long)LTOK * HDIM;
static constexpr long SZ_L3H = (long)LTOK * 3 * HDIM;
static constexpr long SZ_LMH = (long)LTOK * MHID;

static constexpr long F_X    = 0;
static constexpr long F_RES  = F_X   + SZ_LH;
static constexpr long F_HB   = F_RES + SZ_LH;
static constexpr long F_QKV  = F_HB  + SZ_LH;
static constexpr long F_GATE = F_QKV + SZ_L3H;
static constexpr long F_UP   = F_GATE + SZ_LMH;
static constexpr long F_TOTAL = F_UP + SZ_LMH;
__device__ float g_f32[F_TOTAL];

// ---------------- bf16 scratch (hi/lo pairs) ----------------
static constexpr long SZ_XS  = (long)LTOK * PDIM;
static constexpr long SZ_PW  = (long)PDIM * HDIM;
static constexpr long SZ_QW  = (long)NBLK * HDIM * 3*HDIM;
static constexpr long SZ_PRW = (long)NBLK * HDIM * HDIM;
static constexpr long SZ_GWP = (long)NBLK * HDIM * MH_P;   // padded
static constexpr long SZ_DW  = (long)NBLK * MHID * HDIM;
static constexpr long SZ_M0W = (long)H4 * H4;
static constexpr long SZ_M2W = (long)H4 * DMODEL;
static constexpr long SZ_SHP = (long)LTOK * MH_P;          // padded swiglu out

static constexpr long B_XH  = 0;
static constexpr long B_XL  = B_XH + SZ_XS;
static constexpr long B_NH  = B_XL + SZ_XS;
static constexpr long B_NL  = B_NH + SZ_LH;
static constexpr long B_AH  = B_NL + SZ_LH;
static constexpr long B_AL  = B_AH + SZ_LH;
static constexpr long B_SH  = B_AL + SZ_LH;
static constexpr long B_SL  = B_SH + SZ_SHP;
static constexpr long B_PW  = B_SL + SZ_SHP;
static constexpr long B_QW  = B_PW + 2*SZ_PW;
static constexpr long B_PRW = B_QW + 2*SZ_QW;
static constexpr long B_GW  = B_PRW + 2*SZ_PRW;
static constexpr long B_UW  = B_GW + 2*SZ_GWP;
static constexpr long B_DW  = B_UW + 2*SZ_GWP;
static constexpr long B_M0W = B_DW + 2*SZ_DW;
static constexpr long B_M2W = B_M0W + 2*SZ_M0W;
static constexpr long B_TOTAL = B_M2W + 2*SZ_M2W;
__device__ __nv_bfloat16 g_bf16[B_TOTAL];

// ---------------- PTX helpers (base sm_103 target only!) ----------------
__device__ __forceinline__ uint32_t smem_to_u32(const void* p) {
    uint32_t a;
    asm("{ .reg .u64 t; cvta.to.shared.u64 t, %1; cvt.u32.u64 %0, t; }" : "=r"(a) : "l"(p));
    return a;
}
__device__ __forceinline__ void cp16(uint32_t dst, const void* src, int bytes) {
    asm volatile("cp.async.cg.shared.global [%0], [%1], 16, %2;"
                 :: "r"(dst), "l"(src), "r"(bytes));
}
#define CP_COMMIT() asm volatile("cp.async.commit_group;" ::: "memory")
#define CP_WAIT2()  asm volatile("cp.async.wait_group 2;" ::: "memory")

__device__ __forceinline__ void ldsm_x4(uint32_t r[4], uint32_t addr) {
    asm volatile("ldmatrix.sync.aligned.m8n8.x4.shared.b16 {%0,%1,%2,%3}, [%4];"
                 : "=r"(r[0]), "=r"(r[1]), "=r"(r[2]), "=r"(r[3]) : "r"(addr));
}
__device__ __forceinline__ void ldsm_x4t(uint32_t r[4], uint32_t addr) {
    asm volatile("ldmatrix.sync.aligned.m8n8.x4.trans.shared.b16 {%0,%1,%2,%3}, [%4];"
                 : "=r"(r[0]), "=r"(r[1]), "=r"(r[2]), "=r"(r[3]) : "r"(addr));
}
__device__ __forceinline__ void mma_bf16(float c[4], const uint32_t a[4],
                                         uint32_t b0, uint32_t b1) {
    asm volatile(
        "mma.sync.aligned.m16n8k16.row.col.f32.bf16.bf16.f32 "
        "{%0,%1,%2,%3}, {%4,%5,%6,%7}, {%8,%9}, {%0,%1,%2,%3};"
        : "+f"(c[0]), "+f"(c[1]), "+f"(c[2]), "+f"(c[3])
        : "r"(a[0]), "r"(a[1]), "r"(a[2]), "r"(a[3]), "r"(b0), "r"(b1));
}

// ---------------- tensor-core GEMM (bf16x3 split, fp32 accum) ----------------
enum { E_NONE = 0, E_BIAS = 1, E_BIAS_RES = 2, E_GELU_SPLIT = 3 };

// Tiles: BM=128, BN=128, BK=32. 8 warps in 2(M)x4(N); warp tile 64x32.
// Launch bounds (256, 2): cap regs at 128 so 2 CTAs co-reside per SM.
#define A_STRIDE 40
#define B_STRIDE 136
#define A_TILE_B (128 * A_STRIDE * 2)      // 10240
#define B_TILE_B (32 * B_STRIDE * 2)       // 8704
#define STAGE_B  (2 * A_TILE_B + 2 * B_TILE_B)  // 37888
#define OFF_AH 0
#define OFF_AL A_TILE_B
#define OFF_BH (2 * A_TILE_B)
#define OFF_BL (2 * A_TILE_B + B_TILE_B)
#define GEMM_SMEM (3 * STAGE_B)            // 113664
#define GT 256

template<int EPI>
__global__ void __launch_bounds__(GT, 2) tcgemm_kernel(
    const __nv_bfloat16* __restrict__ Ah, const __nv_bfloat16* __restrict__ Al,
    const __nv_bfloat16* __restrict__ Bh, const __nv_bfloat16* __restrict__ Bl,
    const float* __restrict__ bias, const float* __restrict__ res,
    float* __restrict__ C, __nv_bfloat16* __restrict__ Oh, __nv_bfloat16* __restrict__ Ol,
    int M, int N, int K, int lda, int ldb, int ldc)
{
    extern __shared__ __align__(16) char sm[];
    const uint32_t smem_u = smem_to_u32(sm);
    const int tid = threadIdx.x;
    const int lane = tid & 31, wid = tid >> 5;
    const int wm = wid >> 2, wn = wid & 3;        // 2(M) x 4(N) warp grid
    const int row0 = blockIdx.y * 128, col0 = blockIdx.x * 128;

    const int nc = (K + 31) / 32;

    // -------- stage loader --------
    auto load_stage = [&](int st, int c) {
        const uint32_t sbase = smem_u + st * STAGE_B;
        const int k0 = c * 32;
        // A tiles: 128 rows x 32 bf16 (4 x 16B per row); 512 vecs per half
        #pragma unroll
        for (int h = 0; h < 2; ++h) {
            const __nv_bfloat16* src = h ? Al : Ah;
            const uint32_t dbase = sbase + (h ? OFF_AL : OFF_AH);
            #pragma unroll
            for (int it = 0; it < 2; ++it) {
                int e = tid + it * 256;
                int r = e >> 2, q = e & 3;
                int gr = row0 + r;
                int gk = k0 + q * 8;
                int bytes = (K - gk) * 2;
                bytes = bytes < 0 ? 0 : (bytes > 16 ? 16 : bytes);
                const __nv_bfloat16* g = src + (long)gr * lda + (bytes > 0 ? gk : 0);
                cp16(dbase + r * (A_STRIDE * 2) + q * 16, g, bytes);
            }
        }
        // B tiles: 32 rows x 128 bf16 (16 x 16B per row); 512 vecs per half
        #pragma unroll
        for (int h = 0; h < 2; ++h) {
            const __nv_bfloat16* src = h ? Bl : Bh;
            const uint32_t dbase = sbase + (h ? OFF_BL : OFF_BH);
            #pragma unroll
            for (int it = 0; it < 2; ++it) {
                int e = tid + it * 256;
                int r = e >> 4, q = e & 15;
                int gk = k0 + r;
                int gc = col0 + q * 8;
                int bytes = (N - gc) * 2;
                bytes = bytes < 0 ? 0 : (bytes > 16 ? 16 : bytes);
                if (gk >= K) bytes = 0;
                const __nv_bfloat16* g = src + (long)(gk < K ? gk : 0) * ldb + (bytes > 0 ? gc : 0);
                cp16(dbase + r * (B_STRIDE * 2) + q * 16, g, bytes);
            }
        }
    };

    // -------- ldmatrix lane offsets --------
    const int a_row = lane & 15;
    const int a_kh = (lane >> 4) * 8;
    const int b_g = lane >> 3, b_l = lane & 7;
    const int b_k = (b_g & 1) * 8 + b_l;
    const int b_n = (b_g >> 1) * 8;

    float acc[4][4][4];
    #pragma unroll
    for (int i = 0; i < 4; ++i)
        #pragma unroll
        for (int j = 0; j < 4; ++j)
            #pragma unroll
            for (int r = 0; r < 4; ++r) acc[i][j][r] = 0.f;

    // prologue
    #pragma unroll
    for (int s = 0; s < 3; ++s) {
        if (s < nc) load_stage(s, s);
        CP_COMMIT();
    }

    for (int c = 0; c < nc; ++c) {
        CP_WAIT2();
        __syncthreads();
        const int st = c % 3;
        const uint32_t sbase = smem_u + st * STAGE_B;
        const uint32_t aB[2] = { sbase + OFF_AH, sbase + OFF_AL };
        const uint32_t bB[2] = { sbase + OFF_BH, sbase + OFF_BL };

        #pragma unroll
        for (int ks = 0; ks < 2; ++ks) {
            uint32_t af[2][4][4];
            #pragma unroll
            for (int h = 0; h < 2; ++h)
                #pragma unroll
                for (int i = 0; i < 4; ++i)
                    ldsm_x4(af[h][i],
                        aB[h] + 2u * ((wm * 64 + i * 16 + a_row) * A_STRIDE + ks * 16 + a_kh));
            // stream B fragments per 16-column block (keeps live regs < 128)
            #pragma unroll
            for (int j2 = 0; j2 < 2; ++j2) {
                uint32_t b0[4], b1[4];
                uint32_t boff = 2u * ((ks * 16 + b_k) * B_STRIDE + wn * 32 + j2 * 16 + b_n);
                ldsm_x4t(b0, bB[0] + boff);
                ldsm_x4t(b1, bB[1] + boff);
                #pragma unroll
                for (int i = 0; i < 4; ++i) {
                    // Ah*Bh
                    mma_bf16(acc[i][2*j2],   af[0][i], b0[0], b0[1]);
                    mma_bf16(acc[i][2*j2+1], af[0][i], b0[2], b0[3]);
                    // Ah*Bl
                    mma_bf16(acc[i][2*j2],   af[0][i], b1[0], b1[1]);
                    mma_bf16(acc[i][2*j2+1], af[0][i], b1[2], b1[3]);
                    // Al*Bh
                    mma_bf16(acc[i][2*j2],   af[1][i], b0[0], b0[1]);
                    mma_bf16(acc[i][2*j2+1], af[1][i], b0[2], b0[3]);
                }
            }
        }
        __syncthreads();
        if (c + 3 < nc) load_stage(st, c + 3);
        CP_COMMIT();
    }

    // -------- epilogue --------
    const int g = lane >> 2, t = lane & 3;
    #pragma unroll
    for (int i = 0; i < 4; ++i) {
        #pragma unroll
        for (int j = 0; j < 4; ++j) {
            int col = col0 + wn * 32 + j * 8 + t * 2;
            if (col >= N) continue;
            float b0 = 0.f, b1 = 0.f;
            if (EPI != E_NONE) { b0 = bias[col]; b1 = bias[col + 1]; }
            #pragma unroll
            for (int rr = 0; rr < 2; ++rr) {
                int row = row0 + wm * 64 + i * 16 + g + rr * 8;
                if (row >= M) continue;
                float v0 = acc[i][j][rr * 2 + 0] + b0;
                float v1 = acc[i][j][rr * 2 + 1] + b1;
                long idx = (long)row * ldc + col;
                if (EPI == E_BIAS_RES) { v0 += res[idx]; v1 += res[idx + 1]; }
                if (EPI == E_GELU_SPLIT) {
                    v0 = 0.5f * v0 * (1.f + erff(v0 * 0.70710678118654752f));
                    v1 = 0.5f * v1 * (1.f + erff(v1 * 0.70710678118654752f));
                    __nv_bfloat16 h0 = __float2bfloat16(v0);
                    __nv_bfloat16 h1 = __float2bfloat16(v1);
                    Oh[idx] = h0; Oh[idx + 1] = h1;
                    Ol[idx]     = __float2bfloat16(v0 - __bfloat162float(h0));
                    Ol[idx + 1] = __float2bfloat16(v1 - __bfloat162float(h1));
                } else {
                    float2 o = make_float2(v0, v1);
                    *reinterpret_cast<float2*>(C + idx) = o;
                }
            }
        }
    }
}

// ---------------- fused windowed attention with inline RoPE (fp32) ----------------
#define SP 81
#define ATTN_SMEM ((3 * 64 * SP + 64 * 64) * 4)

__global__ void __launch_bounds__(256) attn_kernel(
    const float* __restrict__ qkv, const float* __restrict__ cosb,
    const float* __restrict__ sinb, __nv_bfloat16* __restrict__ outH,
    __nv_bfloat16* __restrict__ outL)
{
    extern __shared__ float smf[];
    float* q = smf;
    float* k = smf + 64 * SP;
    float* v = smf + 2 * 64 * SP;
    float* s = smf + 3 * 64 * SP;

    const int w = blockIdx.x >> 4;
    const int h = blockIdx.x & 15;
    const int tid = threadIdx.x;
    const float scale = 0.11180339887498949f;

    for (int e = tid; e < 64 * 80; e += 256) {
        int t = e / 80, j = e % 80;
        int l = w * 64 + t;
        long base = (long)l * (3 * HDIM) + h * 80;
        float c = cosb[l * 80 + j], sn = sinb[l * 80 + j];
        float qv = qkv[base + j];
        float qr = (j < 40) ? -qkv[base + j + 40] : qkv[base + j - 40];
        q[t * SP + j] = qv * c + qr * sn;
        float kv = qkv[base + HDIM + j];
        float kr = (j < 40) ? -qkv[base + HDIM + j + 40] : qkv[base + HDIM + j - 40];
        k[t * SP + j] = kv * c + kr * sn;
        v[t * SP + j] = qkv[base + 2 * HDIM + j];
    }
    __syncthreads();

    {
        const int tx = tid & 15, ty = tid >> 4;
        float acc[4][4] = {};
        for (int d = 0; d < 80; d++) {
            float qa[4], kb[4];
            #pragma unroll
            for (int i = 0; i < 4; i++) qa[i] = q[(ty * 4 + i) * SP + d];
            #pragma unroll
            for (int j = 0; j < 4; j++) kb[j] = k[(tx * 4 + j) * SP + d];
            #pragma unroll
            for (int i = 0; i < 4; i++)
                #pragma unroll
                for (int j = 0; j < 4; j++)
                    acc[i][j] += qa[i] * kb[j];
        }
        #pragma unroll
        for (int i = 0; i < 4; i++)
            #pragma unroll
            for (int j = 0; j < 4; j++)
                s[(ty * 4 + i) * 64 + tx * 4 + j] = acc[i][j] * scale;
    }
    __syncthreads();

    {
        const int warp = tid >> 5, lane = tid & 31;
        for (int r = warp; r < 64; r += 8) {
            float x0 = s[r * 64 + lane], x1 = s[r * 64 + 32 + lane];
            float mx = fmaxf(x0, x1);
            #pragma unroll
            for (int o = 16; o > 0; o >>= 1) mx = fmaxf(mx, __shfl_xor_sync(~0u, mx, o));
            float e0 = __expf(x0 - mx), e1 = __expf(x1 - mx);
            float sum = e0 + e1;
            #pragma unroll
            for (int o = 16; o > 0; o >>= 1) sum += __shfl_xor_sync(~0u, sum, o);
            float inv = 1.f / sum;
            s[r * 64 + lane] = e0 * inv;
            s[r * 64 + 32 + lane] = e1 * inv;
        }
    }
    __syncthreads();

    {
        const int tx = tid & 15, ty = tid >> 4;
        float acc[4][5] = {};
        for (int kk = 0; kk < 64; kk++) {
            float sa[4], vb[5];
            #pragma unroll
            for (int i = 0; i < 4; i++) sa[i] = s[(ty * 4 + i) * 64 + kk];
            #pragma unroll
            for (int j = 0; j < 5; j++) vb[j] = v[kk * SP + tx * 5 + j];
            #pragma unroll
            for (int i = 0; i < 4; i++)
                #pragma unroll
                for (int j = 0; j < 5; j++)
                    acc[i][j] += sa[i] * vb[j];
        }
        #pragma unroll
        for (int i = 0; i < 4; i++) {
            long obase = (long)(w * 64 + ty * 4 + i) * HDIM + h * 80 + tx * 5;
            #pragma unroll
            for (int j = 0; j < 5; j++) {
                float val = acc[i][j];
                __nv_bfloat16 hh = __float2bfloat16(val);
                outH[obase + j] = hh;
                outL[obase + j] = __float2bfloat16(val - __bfloat162float(hh));
            }
        }
    }
}

// ---------------- fused (optional add) + RMSNorm, bf16 hi/lo out ----------------
__global__ void __launch_bounds__(256) rmsnorm_kernel(
    const float* __restrict__ a, const float* __restrict__ b,
    const float* __restrict__ w, float* __restrict__ sum_out,
    __nv_bfloat16* __restrict__ nh, __nv_bfloat16* __restrict__ nl)
{
    __shared__ float sv[HDIM];
    __shared__ float red[8];
    __shared__ float s_scale;
    const int row = blockIdx.x, tid = threadIdx.x;
    const long base = (long)row * HDIM;
    float ss = 0.f;
    for (int j = tid; j < HDIM; j += 256) {
        float v = a[base + j];
        if (b) v += b[base + j];
        sv[j] = v;
        if (sum_out) sum_out[base + j] = v;
        ss += v * v;
    }
    #pragma unroll
    for (int o = 16; o > 0; o >>= 1) ss += __shfl_xor_sync(~0u, ss, o);
    if ((tid & 31) == 0) red[tid >> 5] = ss;
    __syncthreads();
    if (tid == 0) {
        float t = 0.f;
        #pragma unroll
        for (int i = 0; i < 8; i++) t += red[i];
        s_scale = rsqrtf(t / (float)HDIM + 1e-6f);
    }
    __syncthreads();
    float sc = s_scale;
    for (int j = tid; j < HDIM; j += 256) {
        float v = sv[j] * sc * w[j];
        __nv_bfloat16 hh = __float2bfloat16(v);
        nh[base + j] = hh;
        nl[base + j] = __float2bfloat16(v - __bfloat162float(hh));
    }
}

// ---------------- SwiGLU with bf16 hi/lo out (padded output stride) ----------------
__global__ void __launch_bounds__(256) swiglu_kernel(
    const float* __restrict__ g, const float* __restrict__ u,
    __nv_bfloat16* __restrict__ oh, __nv_bfloat16* __restrict__ ol,
    int rows, int cols, int ldo)
{
    int i = blockIdx.x * 256 + threadIdx.x;
    int total = rows * cols;
    if (i < total) {
        int r = i / cols;
        int c = i - r * cols;
        float x = g[i];
        float sig = 1.f / (1.f + __expf(-x));
        float v = x * sig * u[i];
        __nv_bfloat16 hh = __float2bfloat16(v);
        long o = (long)r * ldo + c;
        oh[o] = hh;
        ol[o] = __float2bfloat16(v - __bfloat162float(hh));
    }
}

// ---------------- fp32 -> bf16 hi/lo split (contiguous) ----------------
__global__ void __launch_bounds__(256) split_kernel(
    const float4* __restrict__ in, __nv_bfloat16* __restrict__ h,
    __nv_bfloat16* __restrict__ l, long n4)
{
    for (long i = (long)blockIdx.x * 256 + threadIdx.x; i < n4; i += (long)gridDim.x * 256) {
        float4 v = in[i];
        __nv_bfloat16 th[4], tl[4];
        float vv[4] = {v.x, v.y, v.z, v.w};
        #pragma unroll
        for (int j = 0; j < 4; j++) {
            th[j] = __float2bfloat16(vv[j]);
            tl[j] = __float2bfloat16(vv[j] - __bfloat162float(th[j]));
        }
        *reinterpret_cast<uint2*>(h + 4 * i) = *reinterpret_cast<uint2*>(th);
        *reinterpret_cast<uint2*>(l + 4 * i) = *reinterpret_cast<uint2*>(tl);
    }
}

// ---------------- fp32 -> bf16 hi/lo split with padded output stride ----------------
__global__ void __launch_bounds__(256) split_pad_kernel(
    const float* __restrict__ in, __nv_bfloat16* __restrict__ h,
    __nv_bfloat16* __restrict__ l, int rows, int cols, int ldo)
{
    int c4n = cols >> 2;
    long total = (long)rows * c4n;
    for (long i = (long)blockIdx.x * 256 + threadIdx.x; i < total; i += (long)gridDim.x * 256) {
        int r = (int)(i / c4n);
        int c4 = (int)(i - (long)r * c4n);
        float4 v = *reinterpret_cast<const float4*>(in + (long)r * cols + c4 * 4);
        __nv_bfloat16 th[4], tl[4];
        float vv[4] = {v.x, v.y, v.z, v.w};
        #pragma unroll
        for (int j = 0; j < 4; j++) {
            th[j] = __float2bfloat16(vv[j]);
            tl[j] = __float2bfloat16(vv[j] - __bfloat162float(th[j]));
        }
        long o = (long)r * ldo + c4 * 4;
        *reinterpret_cast<uint2*>(h + o) = *reinterpret_cast<uint2*>(th);
        *reinterpret_cast<uint2*>(l + o) = *reinterpret_cast<uint2*>(tl);
    }
}

// ---------------- host ----------------
static inline dim3 ggrid(int M, int N) { return dim3((N + 127) / 128, (M + 127) / 128); }

static inline void do_split(const float* src, __nv_bfloat16* h, __nv_bfloat16* l, long n) {
    long n4 = n / 4;
    int blocks = (int)((n4 + 255) / 256);
    if (blocks > 16384) blocks = 16384;
    split_kernel<<<blocks, 256>>>((const float4*)src, h, l, n4);
}
static inline void do_split_pad(const float* src, __nv_bfloat16* h, __nv_bfloat16* l,
                                int rows, int cols, int ldo) {
    long total = (long)rows * (cols / 4);
    int blocks = (int)((total + 255) / 256);
    if (blocks > 16384) blocks = 16384;
    split_pad_kernel<<<blocks, 256>>>(src, h, l, rows, cols, ldo);
}

extern "C" void kernel_launch(void* const* d_in, const int* in_sizes, int n_in,
                              void* d_out, int out_size)
{
    const float* x       = (const float*)d_in[0];
    const float* cosb    = (const float*)d_in[1];
    const float* sinb    = (const float*)d_in[2];
    const float* patch_w = (const float*)d_in[3];
    const float* norm1_w = (const float*)d_in[4];
    const float* norm2_w = (const float*)d_in[5];
    const float* qkv_w   = (const float*)d_in[6];
    const float* qkv_b   = (const float*)d_in[7];
    const float* proj_w  = (const float*)d_in[8];
    const float* proj_b  = (const float*)d_in[9];
    const float* gate_w  = (const float*)d_in[10];
    const float* gate_b  = (const float*)d_in[11];
    const float* up_w    = (const float*)d_in[12];
    const float* up_b    = (const float*)d_in[13];
    const float* down_w  = (const float*)d_in[14];
    const float* down_b  = (const float*)d_in[15];
    const float* lnq_w   = (const float*)d_in[16];
    const float* m0_w    = (const float*)d_in[17];
    const float* m0_b    = (const float*)d_in[18];
    const float* m2_w    = (const float*)d_in[19];
    const float* m2_b    = (const float*)d_in[20];

    float* fs = nullptr;
    __nv_bfloat16* bs = nullptr;
    cudaGetSymbolAddress((void**)&fs, g_f32);
    cudaGetSymbolAddress((void**)&bs, g_bf16);

    float* pX    = fs + F_X;
    float* pRES  = fs + F_RES;
    float* pHB   = fs + F_HB;
    float* pQKV  = fs + F_QKV;
    float* pGATE = fs + F_GATE;
    float* pUP   = fs + F_UP;

    __nv_bfloat16 *xH = bs+B_XH, *xL = bs+B_XL;
    __nv_bfloat16 *nH = bs+B_NH, *nL = bs+B_NL;
    __nv_bfloat16 *aH = bs+B_AH, *aL = bs+B_AL;
    __nv_bfloat16 *sH = bs+B_SH, *sL = bs+B_SL;
    __nv_bfloat16 *pwH = bs+B_PW,  *pwL = pwH + SZ_PW;
    __nv_bfloat16 *qwH = bs+B_QW,  *qwL = qwH + SZ_QW;
    __nv_bfloat16 *prH = bs+B_PRW, *prL = prH + SZ_PRW;
    __nv_bfloat16 *gwH = bs+B_GW,  *gwL = gwH + SZ_GWP;
    __nv_bfloat16 *uwH = bs+B_UW,  *uwL = uwH + SZ_GWP;
    __nv_bfloat16 *dwH = bs+B_DW,  *dwL = dwH + SZ_DW;
    __nv_bfloat16 *m0H = bs+B_M0W, *m0L = m0H + SZ_M0W;
    __nv_bfloat16 *m2H = bs+B_M2W, *m2L = m2H + SZ_M2W;

    cudaFuncSetAttribute(tcgemm_kernel<E_NONE>, cudaFuncAttributeMaxDynamicSharedMemorySize, GEMM_SMEM);
    cudaFuncSetAttribute(tcgemm_kernel<E_BIAS>, cudaFuncAttributeMaxDynamicSharedMemorySize, GEMM_SMEM);
    cudaFuncSetAttribute(tcgemm_kernel<E_BIAS_RES>, cudaFuncAttributeMaxDynamicSharedMemorySize, GEMM_SMEM);
    cudaFuncSetAttribute(tcgemm_kernel<E_GELU_SPLIT>, cudaFuncAttributeMaxDynamicSharedMemorySize, GEMM_SMEM);
    cudaFuncSetAttribute(attn_kernel, cudaFuncAttributeMaxDynamicSharedMemorySize, ATTN_SMEM);

    // Launch order: 5 splits, then the patch-embed GEMM as launch #6 so the
    // ncu capture window (-s 5 -c 1) lands on the GEMM kernel.
    do_split(x,       xH,  xL,  SZ_XS);                       // 1
    do_split(patch_w, pwH, pwL, SZ_PW);                       // 2
    do_split(qkv_w,   qwH, qwL, SZ_QW);                       // 3
    do_split(proj_w,  prH, prL, SZ_PRW);                      // 4
    do_split_pad(gate_w, gwH, gwL, NBLK * HDIM, MHID, MH_P);  // 5

    // patch embed: [8192,1176]@[1176,1280]   (launch #6 - profiled)
    tcgemm_kernel<E_NONE><<<ggrid(LTOK, HDIM), GT, GEMM_SMEM>>>(
        xH, xL, pwH, pwL, nullptr, nullptr, pX, nullptr, nullptr,
        LTOK, HDIM, PDIM, PDIM, HDIM, HDIM);

    do_split_pad(up_w,   uwH, uwL, NBLK * HDIM, MHID, MH_P);
    do_split(down_w,  dwH, dwL, SZ_DW);
    do_split(m0_w,    m0H, m0L, SZ_M0W);
    do_split(m2_w,    m2H, m2L, SZ_M2W);
    cudaMemsetAsync(pRES, 0, SZ_LH * sizeof(float));

    for (int d = 0; d < NBLK; d++) {
        rmsnorm_kernel<<<LTOK, 256>>>(pX, pRES, norm1_w + (long)d * HDIM, pHB, nH, nL);
        tcgemm_kernel<E_BIAS><<<ggrid(LTOK, 3 * HDIM), GT, GEMM_SMEM>>>(
            nH, nL, qwH + (long)d * HDIM * 3 * HDIM, qwL + (long)d * HDIM * 3 * HDIM,
            qkv_b + (long)d * 3 * HDIM, nullptr, pQKV, nullptr, nullptr,
            LTOK, 3 * HDIM, HDIM, HDIM, 3 * HDIM, 3 * HDIM);
        attn_kernel<<<NWIN * NHEAD, 256, ATTN_SMEM>>>(pQKV, cosb, sinb, aH, aL);
        tcgemm_kernel<E_BIAS_RES><<<ggrid(LTOK, HDIM), GT, GEMM_SMEM>>>(
            aH, aL, prH + (long)d * HDIM * HDIM, prL + (long)d * HDIM * HDIM,
            proj_b + (long)d * HDIM, pHB, pRES, nullptr, nullptr,
            LTOK, HDIM, HDIM, HDIM, HDIM, HDIM);
        rmsnorm_kernel<<<LTOK, 256>>>(pRES, nullptr, norm2_w + (long)d * HDIM, nullptr, nH, nL);
        tcgemm_kernel<E_BIAS><<<ggrid(LTOK, MHID), GT, GEMM_SMEM>>>(
            nH, nL, gwH + (long)d * HDIM * MH_P, gwL + (long)d * HDIM * MH_P,
            gate_b + (long)d * MHID, nullptr, pGATE, nullptr, nullptr,
            LTOK, MHID, HDIM, HDIM, MH_P, MHID);
        tcgemm_kernel<E_BIAS><<<ggrid(LTOK, MHID), GT, GEMM_SMEM>>>(
            nH, nL, uwH + (long)d * HDIM * MH_P, uwL + (long)d * HDIM * MH_P,
            up_b + (long)d * MHID, nullptr, pUP, nullptr, nullptr,
            LTOK, MHID, HDIM, HDIM, MH_P, MHID);
        swiglu_kernel<<<(unsigned)(((long)LTOK * MHID + 255) / 256), 256>>>(
            pGATE, pUP, sH, sL, LTOK, MHID, MH_P);
        tcgemm_kernel<E_BIAS><<<ggrid(LTOK, HDIM), GT, GEMM_SMEM>>>(
            sH, sL, dwH + (long)d * MHID * HDIM, dwL + (long)d * MHID * HDIM,
            down_b + (long)d * HDIM, nullptr, pX, nullptr, nullptr,
            LTOK, HDIM, MHID, MH_P, HDIM, HDIM);
    }

    // merger
    rmsnorm_kernel<<<LTOK, 256>>>(pX, pRES, lnq_w, nullptr, nH, nL);
    tcgemm_kernel<E_GELU_SPLIT><<<ggrid(LMERG, H4), GT, GEMM_SMEM>>>(
        nH, nL, m0H, m0L, m0_b, nullptr, nullptr, aH, aL,
        LMERG, H4, H4, H4, H4, H4);
    tcgemm_kernel<E_BIAS><<<ggrid(LMERG, DMODEL), GT, GEMM_SMEM>>>(
        aH, aL, m2H, m2L, m2_b, nullptr, (float*)d_out, nullptr, nullptr,
        LMERG, DMODEL, H4, H4, DMODEL, DMODEL);
}